// round 4
// baseline (speedup 1.0000x reference)
#include <cuda_runtime.h>
#include <cuda_bf16.h>

#define ERRF 1e-12f
constexpr int LEN = 2048;
constexpr int DIM = 64;
constexpr int NT  = 16;      // 16 j-tiles of 128
constexpr int BHN = 32;

// smem layout (bytes): A hi @0, A lo @16K, B bufs @32K: buf*32K + {hi:0, lo:16K}
constexpr int OFF_ALO = 16384;
constexpr int OFF_B   = 32768;
constexpr int SMEM_TOTAL = 98304;   // 96 KB -> 2 CTAs/SM

#define SWZ(o) ((o) ^ (((o) >> 3) & 0x70))

__device__ __forceinline__ unsigned smem_u32(const void* p) {
    return (unsigned)__cvta_generic_to_shared(p);
}
__device__ __forceinline__ float fast_lg2(float x) { float y; asm("lg2.approx.f32 %0, %1;" : "=f"(y) : "f"(x)); return y; }
__device__ __forceinline__ float fast_ex2(float x) { float y; asm("ex2.approx.f32 %0, %1;" : "=f"(y) : "f"(x)); return y; }

__device__ __forceinline__ void ldsm4(unsigned addr, unsigned& r0, unsigned& r1, unsigned& r2, unsigned& r3) {
    asm volatile("ldmatrix.sync.aligned.m8n8.x4.shared.b16 {%0,%1,%2,%3}, [%4];"
                 : "=r"(r0), "=r"(r1), "=r"(r2), "=r"(r3) : "r"(addr));
}

__device__ __forceinline__ void mma16816(float* c, unsigned a0, unsigned a1, unsigned a2, unsigned a3,
                                         unsigned b0, unsigned b1) {
    asm volatile("mma.sync.aligned.m16n8k16.row.col.f32.bf16.bf16.f32 "
                 "{%0,%1,%2,%3}, {%4,%5,%6,%7}, {%8,%9}, {%0,%1,%2,%3};"
                 : "+f"(c[0]), "+f"(c[1]), "+f"(c[2]), "+f"(c[3])
                 : "r"(a0), "r"(a1), "r"(a2), "r"(a3), "r"(b0), "r"(b1));
}

__device__ __forceinline__ unsigned pk(float a, float b) {
    __nv_bfloat162 t(__float2bfloat16(a), __float2bfloat16(b));
    return *reinterpret_cast<unsigned*>(&t);
}

// split fp32 x4 into bf16 hi/lo packed pairs
__device__ __forceinline__ void split4(float x0, float x1, float x2, float x3,
                                       uint2& hi, uint2& lo) {
    __nv_bfloat16 h0 = __float2bfloat16(x0), h1 = __float2bfloat16(x1);
    __nv_bfloat16 h2 = __float2bfloat16(x2), h3 = __float2bfloat16(x3);
    hi = make_uint2(pk(x0, x1), pk(x2, x3));   // pk re-rounds; identical to h*
    lo = make_uint2(pk(x0 - __bfloat162float(h0), x1 - __bfloat162float(h1)),
                    pk(x2 - __bfloat162float(h2), x3 - __bfloat162float(h3)));
}

// Load 128x64 fp32 rows (base row0), scale by sqrt(w+eps), split, store K-major SW128.
__device__ __forceinline__ void load_tile(const float* __restrict__ kb,
                                          const float* __restrict__ wv,
                                          int row0, char* smem, int off_hi, int tid) {
    const int f4 = tid & 15;
    const int rg = tid >> 4;
    #pragma unroll
    for (int p = 0; p < 8; ++p) {
        int r = p * 16 + rg;
        float w = sqrtf(wv[row0 + r] + ERRF);
        float4 v = reinterpret_cast<const float4*>(kb + (size_t)(row0 + r) * DIM)[f4];
        uint2 hi, lo;
        split4(v.x * w, v.y * w, v.z * w, v.w * w, hi, lo);
        unsigned off = SWZ((unsigned)(r * 128 + f4 * 8));
        *reinterpret_cast<uint2*>(smem + off_hi + off) = hi;
        *reinterpret_cast<uint2*>(smem + off_hi + 16384 + off) = lo;
    }
}

__global__ void __launch_bounds__(256, 2)
mha_hmma_kernel(const float* __restrict__ k, const float* __restrict__ src,
                const float* __restrict__ dst, float* __restrict__ out)
{
    extern __shared__ char smem[];
    const int tid = threadIdx.x;
    const int wid = tid >> 5;
    const int lid = tid & 31;
    const int bh  = blockIdx.y;
    const int it0 = blockIdx.x * 128;

    const float* kb = k   + (size_t)bh * LEN * DIM;
    const float* sb = src + (size_t)bh * LEN;
    const float* db = dst + (size_t)bh * LEN;
    float*       ob = out + (size_t)bh * LEN * LEN;

    // Prologue: A tile (rows it0, src weights), B tile 0 (rows 0, dest weights)
    load_tile(kb, sb, it0, smem, 0, tid);
    load_tile(kb, db, 0,   smem, OFF_B, tid);
    __syncthreads();

    // lane-invariant ldmatrix address components
    const int l7  = lid & 7;
    const int sel = lid >> 3;
    const unsigned xk = (unsigned)(l7 << 4);
    const int arow  = wid * 16 + l7 + ((sel & 1) ? 8 : 0);
    const unsigned akoff = (sel & 2) ? 16u : 0u;
    const int bn    = l7 + ((sel & 2) ? 8 : 0);
    const unsigned bkoff = (sel & 1) ? 16u : 0u;
    const unsigned sbase = smem_u32(smem);
    const unsigned a_lane = sbase + (unsigned)(arow * 128);
    const unsigned b_lane = sbase + OFF_B + (unsigned)(bn * 128);

    // epilogue lane mapping
    const int q  = lid & 3;
    const int g4 = lid >> 2;
    const int gi_lo = it0 + wid * 16 + g4;
    const int gi_hi = gi_lo + 8;
    float* const row_lo = ob + (size_t)gi_lo * LEN;
    float* const row_hi = ob + (size_t)gi_hi * LEN;

    float carry_lo = 0.f, carry_hi = 0.f;

    const int pf4 = tid & 15;        // prefetch indexing
    const int prg = tid >> 4;

    for (int jt = 0; jt < NT; ++jt) {
        // ---- GEMM: 3-pass bf16 split, acc 16 rows x 128 cols per warp ----
        float c[16][4];
        #pragma unroll
        for (int nb = 0; nb < 16; ++nb)
            #pragma unroll
            for (int e = 0; e < 4; ++e) c[nb][e] = 0.f;

        const unsigned bbuf = (unsigned)((jt & 1) * 32768);
        #pragma unroll 1
        for (int pass = 0; pass < 3; ++pass) {
            const unsigned apass = (pass == 2) ? (unsigned)OFF_ALO : 0u;
            const unsigned bpass = bbuf + ((pass == 1) ? 16384u : 0u);
            #pragma unroll
            for (int ks = 0; ks < 4; ++ks) {
                unsigned a0, a1, a2, a3;
                ldsm4(a_lane + apass + (((unsigned)(ks * 32) + akoff) ^ xk), a0, a1, a2, a3);
                const unsigned bkb = ((unsigned)(ks * 32) + bkoff) ^ xk;
                #pragma unroll
                for (int np = 0; np < 8; ++np) {
                    unsigned b0, b1, b2, b3;
                    ldsm4(b_lane + bpass + (unsigned)(np * 2048) + bkb, b0, b1, b2, b3);
                    mma16816(c[np * 2],     a0, a1, a2, a3, b0, b1);
                    mma16816(c[np * 2 + 1], a0, a1, a2, a3, b2, b3);
                }
            }
        }

        const int nxt = jt + 1;
        const int jb0 = jt * 128;

        // ---- epilogue helper (macro-ish lambda): transform + scan + store ----
        auto do_nb = [&](int nb) {
            const int col0 = jb0 + nb * 8 + q * 2;
            // row-lo half
            {
                float t0 = fast_ex2(fast_lg2(fmaxf(c[nb][0], 0.f) + ERRF) * 0.66666667f);
                float t1 = fast_ex2(fast_lg2(fmaxf(c[nb][1], 0.f) + ERRF) * 0.66666667f);
                float s = t0 + t1, p = s, o;
                o = __shfl_up_sync(0xffffffffu, p, 1, 4); if (q >= 1) p += o;
                o = __shfl_up_sync(0xffffffffu, p, 2, 4); if (q >= 2) p += o;
                float tot  = __shfl_sync(0xffffffffu, p, 3, 4);
                float excl = carry_lo + p - s;
                float o0 = excl + t0, o1 = excl + s;
                carry_lo += tot;
                float2 st = make_float2(col0 >= gi_lo ? o0 : 0.f,
                                        col0 + 1 >= gi_lo ? o1 : 0.f);
                *reinterpret_cast<float2*>(row_lo + col0) = st;
            }
            // row-hi half
            {
                float t0 = fast_ex2(fast_lg2(fmaxf(c[nb][2], 0.f) + ERRF) * 0.66666667f);
                float t1 = fast_ex2(fast_lg2(fmaxf(c[nb][3], 0.f) + ERRF) * 0.66666667f);
                float s = t0 + t1, p = s, o;
                o = __shfl_up_sync(0xffffffffu, p, 1, 4); if (q >= 1) p += o;
                o = __shfl_up_sync(0xffffffffu, p, 2, 4); if (q >= 2) p += o;
                float tot  = __shfl_sync(0xffffffffu, p, 3, 4);
                float excl = carry_hi + p - s;
                float o0 = excl + t0, o1 = excl + s;
                carry_hi += tot;
                float2 st = make_float2(col0 >= gi_hi ? o0 : 0.f,
                                        col0 + 1 >= gi_hi ? o1 : 0.f);
                *reinterpret_cast<float2*>(row_hi + col0) = st;
            }
        };

        #pragma unroll
        for (int nb = 0; nb < 8; ++nb) do_nb(nb);

        // ---- prefetch next B tile (LDG only) between epilogue halves ----
        float4 pv[8]; float pw[8];
        if (nxt < NT) {
            #pragma unroll
            for (int p = 0; p < 8; ++p) {
                int r = p * 16 + prg;
                pv[p] = reinterpret_cast<const float4*>(kb + (size_t)(nxt * 128 + r) * DIM)[pf4];
                pw[p] = db[nxt * 128 + r];
            }
        }

        #pragma unroll
        for (int nb = 8; nb < 16; ++nb) do_nb(nb);

        if (nxt < NT) {
            char* bdst = smem + OFF_B + (nxt & 1) * 32768;
            #pragma unroll
            for (int p = 0; p < 8; ++p) {
                int r = p * 16 + prg;
                float w = sqrtf(pw[p] + ERRF);
                uint2 hi, lo;
                split4(pv[p].x * w, pv[p].y * w, pv[p].z * w, pv[p].w * w, hi, lo);
                unsigned off = SWZ((unsigned)(r * 128 + pf4 * 8));
                *reinterpret_cast<uint2*>(bdst + off) = hi;
                *reinterpret_cast<uint2*>(bdst + 16384 + off) = lo;
            }
        }
        __syncthreads();
    }
}

extern "C" void kernel_launch(void* const* d_in, const int* in_sizes, int n_in,
                              void* d_out, int out_size) {
    const float* k   = (const float*)d_in[0];
    const float* src = (const float*)d_in[1];
    const float* dst = (const float*)d_in[2];
    float*       out = (float*)d_out;

    cudaFuncSetAttribute(mha_hmma_kernel,
                         cudaFuncAttributeMaxDynamicSharedMemorySize, SMEM_TOTAL);
    (void)in_sizes; (void)n_in; (void)out_size;

    dim3 grid(LEN / 128, BHN);
    mha_hmma_kernel<<<grid, 256, SMEM_TOTAL>>>(k, src, dst, out);
}

// round 6
// speedup vs baseline: 1.4816x; 1.4816x over previous
#include <cuda_runtime.h>
#include <cuda_fp16.h>

#define ERRF 1e-12f
constexpr int LEN = 2048;
constexpr int DIM = 64;
constexpr int NT  = 16;      // 16 j-tiles of 128
constexpr int BHN = 32;

// smem: A hi @0 (16K), A lo @16K, B double-buffer @32K (2 x 16K)
constexpr int OFF_ALO = 16384;
constexpr int OFF_B   = 32768;
constexpr int SMEM_TOTAL = 65536;

#define SWZ(o) ((o) ^ (((o) >> 3) & 0x70))

__device__ __forceinline__ unsigned smem_u32(const void* p) {
    return (unsigned)__cvta_generic_to_shared(p);
}
__device__ __forceinline__ float fast_lg2(float x) { float y; asm("lg2.approx.f32 %0, %1;" : "=f"(y) : "f"(x)); return y; }
__device__ __forceinline__ float fast_ex2(float x) { float y; asm("ex2.approx.f32 %0, %1;" : "=f"(y) : "f"(x)); return y; }

__device__ __forceinline__ void ldsm4(unsigned addr, unsigned& r0, unsigned& r1, unsigned& r2, unsigned& r3) {
    asm volatile("ldmatrix.sync.aligned.m8n8.x4.shared.b16 {%0,%1,%2,%3}, [%4];"
                 : "=r"(r0), "=r"(r1), "=r"(r2), "=r"(r3) : "r"(addr));
}

__device__ __forceinline__ void mma16816(float* c, unsigned a0, unsigned a1, unsigned a2, unsigned a3,
                                         unsigned b0, unsigned b1) {
    asm volatile("mma.sync.aligned.m16n8k16.row.col.f32.f16.f16.f32 "
                 "{%0,%1,%2,%3}, {%4,%5,%6,%7}, {%8,%9}, {%0,%1,%2,%3};"
                 : "+f"(c[0]), "+f"(c[1]), "+f"(c[2]), "+f"(c[3])
                 : "r"(a0), "r"(a1), "r"(a2), "r"(a3), "r"(b0), "r"(b1));
}

__device__ __forceinline__ unsigned pkh(float a, float b) {
    __half2 t = __floats2half2_rn(a, b);
    return *reinterpret_cast<unsigned*>(&t);
}

// B tile: 128 rows x 64 cols fp32 -> single fp16, K-major SW128 rows of 128B.
__device__ __forceinline__ void load_tile_b(const float* __restrict__ kb,
                                            const float* __restrict__ wv,
                                            int row0, char* smem, int off, int tid) {
    const int f4 = tid & 15;
    const int rg = tid >> 4;
    #pragma unroll
    for (int p = 0; p < 8; ++p) {
        int r = p * 16 + rg;
        float w = sqrtf(wv[row0 + r] + ERRF);
        float4 v = reinterpret_cast<const float4*>(kb + (size_t)(row0 + r) * DIM)[f4];
        unsigned o = SWZ((unsigned)(r * 128 + f4 * 8));
        *reinterpret_cast<uint2*>(smem + off + o) =
            make_uint2(pkh(v.x * w, v.y * w), pkh(v.z * w, v.w * w));
    }
}

// A tile: fp16 hi + lo split
__device__ __forceinline__ void load_tile_a(const float* __restrict__ kb,
                                            const float* __restrict__ wv,
                                            int row0, char* smem, int tid) {
    const int f4 = tid & 15;
    const int rg = tid >> 4;
    #pragma unroll
    for (int p = 0; p < 8; ++p) {
        int r = p * 16 + rg;
        float w = sqrtf(wv[row0 + r] + ERRF);
        float4 v = reinterpret_cast<const float4*>(kb + (size_t)(row0 + r) * DIM)[f4];
        float x0 = v.x * w, x1 = v.y * w, x2 = v.z * w, x3 = v.w * w;
        __half h0 = __float2half_rn(x0), h1 = __float2half_rn(x1);
        __half h2 = __float2half_rn(x2), h3 = __float2half_rn(x3);
        unsigned o = SWZ((unsigned)(r * 128 + f4 * 8));
        *reinterpret_cast<uint2*>(smem + o) = make_uint2(pkh(x0, x1), pkh(x2, x3));
        *reinterpret_cast<uint2*>(smem + OFF_ALO + o) =
            make_uint2(pkh(x0 - __half2float(h0), x1 - __half2float(h1)),
                       pkh(x2 - __half2float(h2), x3 - __half2float(h3)));
    }
}

__global__ void __launch_bounds__(256, 2)
mha_hmma2_kernel(const float* __restrict__ k, const float* __restrict__ src,
                 const float* __restrict__ dst, float* __restrict__ out)
{
    extern __shared__ char smem[];
    const int tid = threadIdx.x;
    const int wid = tid >> 5;
    const int lid = tid & 31;
    const int bh  = blockIdx.y;
    const int diag = blockIdx.x;          // j-tile index containing the diagonal
    const int it0 = blockIdx.x * 128;

    const float* kb = k   + (size_t)bh * LEN * DIM;
    const float* sb = src + (size_t)bh * LEN;
    const float* db = dst + (size_t)bh * LEN;
    float*       ob = out + (size_t)bh * LEN * LEN;

    load_tile_a(kb, sb, it0, smem, tid);
    load_tile_b(kb, db, 0, smem, OFF_B, tid);
    __syncthreads();

    // ldmatrix lane addressing (fp16, 128B K-major rows, SW128)
    const int l7  = lid & 7;
    const int sel = lid >> 3;
    const unsigned xk = (unsigned)(l7 << 4);
    const int arow  = wid * 16 + l7 + ((sel & 1) ? 8 : 0);
    const unsigned akoff = (sel & 2) ? 16u : 0u;
    const int bn    = l7 + ((sel & 2) ? 8 : 0);
    const unsigned bkoff = (sel & 1) ? 16u : 0u;
    const unsigned sbase = smem_u32(smem);
    const unsigned a_lane = sbase + (unsigned)(arow * 128);
    const unsigned b_lane = sbase + OFF_B + (unsigned)(bn * 128);

    // epilogue lane mapping
    const int q  = lid & 3;
    const int g4 = lid >> 2;
    const int gi_lo = it0 + wid * 16 + g4;
    const int gi_hi = gi_lo + 8;
    float* const row_lo = ob + (size_t)gi_lo * LEN;
    float* const row_hi = ob + (size_t)gi_hi * LEN;

    float carry_lo = 0.f, carry_hi = 0.f;   // full row prefix (scan phase)
    float part_lo = 0.f,  part_hi = 0.f;    // lane-partial sums (below-diag phase)

    const int pf4 = tid & 15;
    const int prg = tid >> 4;

    for (int jt = 0; jt < NT; ++jt) {
        const int jb0 = jt * 128;
        const bool below = (jt < diag);

        // zero-fill stores for fully-masked tiles (independent of GEMM; issue early)
        if (below) {
            const float4 z = make_float4(0.f, 0.f, 0.f, 0.f);
            float* base = ob + (size_t)(it0 + wid * 16) * LEN + jb0 + lid * 4;
            #pragma unroll
            for (int r = 0; r < 16; ++r)
                *reinterpret_cast<float4*>(base + (size_t)r * LEN) = z;
        }

        // ---- GEMM: 2-pass fp16 split (A hi + A lo, single B) ----
        float c[16][4];
        #pragma unroll
        for (int nb = 0; nb < 16; ++nb) {
            #pragma unroll
            for (int e = 0; e < 4; ++e) c[nb][e] = 0.f;
        }

        const unsigned bbuf = (unsigned)((jt & 1) * 16384);
        #pragma unroll
        for (int ks = 0; ks < 4; ++ks) {
            const unsigned ak = ((unsigned)(ks * 32) + akoff) ^ xk;
            unsigned ah0, ah1, ah2, ah3, al0, al1, al2, al3;
            ldsm4(a_lane + ak, ah0, ah1, ah2, ah3);
            ldsm4(a_lane + OFF_ALO + ak, al0, al1, al2, al3);
            const unsigned bkb = ((unsigned)(ks * 32) + bkoff) ^ xk;
            #pragma unroll
            for (int np = 0; np < 8; ++np) {
                unsigned b0, b1, b2, b3;
                ldsm4(b_lane + bbuf + (unsigned)(np * 2048) + bkb, b0, b1, b2, b3);
                mma16816(c[np * 2],     ah0, ah1, ah2, ah3, b0, b1);
                mma16816(c[np * 2 + 1], ah0, ah1, ah2, ah3, b2, b3);
                mma16816(c[np * 2],     al0, al1, al2, al3, b0, b1);
                mma16816(c[np * 2 + 1], al0, al1, al2, al3, b2, b3);
            }
        }

        const int nxt = jt + 1;

        // convert lane-partials to full-row carry at the diagonal tile
        if (jt == diag) {
            float v = part_lo;
            v += __shfl_xor_sync(0xffffffffu, v, 1, 4);
            v += __shfl_xor_sync(0xffffffffu, v, 2, 4);
            carry_lo = v;
            v = part_hi;
            v += __shfl_xor_sync(0xffffffffu, v, 1, 4);
            v += __shfl_xor_sync(0xffffffffu, v, 2, 4);
            carry_hi = v;
        }

        auto scan_store = [&](int nb, bool masked) {
            const int col0 = jb0 + nb * 8 + q * 2;
            {
                float t0 = fast_ex2(fast_lg2(fmaxf(c[nb][0], 0.f) + ERRF) * 0.66666667f);
                float t1 = fast_ex2(fast_lg2(fmaxf(c[nb][1], 0.f) + ERRF) * 0.66666667f);
                float s = t0 + t1, p = s, o;
                o = __shfl_up_sync(0xffffffffu, p, 1, 4); if (q >= 1) p += o;
                o = __shfl_up_sync(0xffffffffu, p, 2, 4); if (q >= 2) p += o;
                float tot  = __shfl_sync(0xffffffffu, p, 3, 4);
                float excl = carry_lo + p - s;
                float o0 = excl + t0, o1 = excl + s;
                carry_lo += tot;
                float2 st = masked ? make_float2(col0 >= gi_lo ? o0 : 0.f,
                                                 col0 + 1 >= gi_lo ? o1 : 0.f)
                                   : make_float2(o0, o1);
                *reinterpret_cast<float2*>(row_lo + col0) = st;
            }
            {
                float t0 = fast_ex2(fast_lg2(fmaxf(c[nb][2], 0.f) + ERRF) * 0.66666667f);
                float t1 = fast_ex2(fast_lg2(fmaxf(c[nb][3], 0.f) + ERRF) * 0.66666667f);
                float s = t0 + t1, p = s, o;
                o = __shfl_up_sync(0xffffffffu, p, 1, 4); if (q >= 1) p += o;
                o = __shfl_up_sync(0xffffffffu, p, 2, 4); if (q >= 2) p += o;
                float tot  = __shfl_sync(0xffffffffu, p, 3, 4);
                float excl = carry_hi + p - s;
                float o0 = excl + t0, o1 = excl + s;
                carry_hi += tot;
                float2 st = masked ? make_float2(col0 >= gi_hi ? o0 : 0.f,
                                                 col0 + 1 >= gi_hi ? o1 : 0.f)
                                   : make_float2(o0, o1);
                *reinterpret_cast<float2*>(row_hi + col0) = st;
            }
        };

        auto accum_only = [&](int nb) {
            float t0 = fast_ex2(fast_lg2(fmaxf(c[nb][0], 0.f) + ERRF) * 0.66666667f);
            float t1 = fast_ex2(fast_lg2(fmaxf(c[nb][1], 0.f) + ERRF) * 0.66666667f);
            part_lo += t0 + t1;
            float t2 = fast_ex2(fast_lg2(fmaxf(c[nb][2], 0.f) + ERRF) * 0.66666667f);
            float t3 = fast_ex2(fast_lg2(fmaxf(c[nb][3], 0.f) + ERRF) * 0.66666667f);
            part_hi += t2 + t3;
        };

        // ---- first epilogue half ----
        if (below) {
            #pragma unroll
            for (int nb = 0; nb < 8; ++nb) accum_only(nb);
        } else if (jt == diag) {
            #pragma unroll
            for (int nb = 0; nb < 8; ++nb) scan_store(nb, true);
        } else {
            #pragma unroll
            for (int nb = 0; nb < 8; ++nb) scan_store(nb, false);
        }

        // prefetch next B tile (LDG) between epilogue halves
        float4 pv[8]; float pw[8];
        if (nxt < NT) {
            #pragma unroll
            for (int p = 0; p < 8; ++p) {
                int r = p * 16 + prg;
                pv[p] = reinterpret_cast<const float4*>(kb + (size_t)(nxt * 128 + r) * DIM)[pf4];
                pw[p] = db[nxt * 128 + r];
            }
        }

        // ---- second epilogue half ----
        if (below) {
            #pragma unroll
            for (int nb = 8; nb < 16; ++nb) accum_only(nb);
        } else if (jt == diag) {
            #pragma unroll
            for (int nb = 8; nb < 16; ++nb) scan_store(nb, true);
        } else {
            #pragma unroll
            for (int nb = 8; nb < 16; ++nb) scan_store(nb, false);
        }

        if (nxt < NT) {
            char* bdst = smem + OFF_B + (nxt & 1) * 16384;
            #pragma unroll
            for (int p = 0; p < 8; ++p) {
                int r = p * 16 + prg;
                float w = sqrtf(pw[p] + ERRF);
                unsigned o = SWZ((unsigned)(r * 128 + pf4 * 8));
                *reinterpret_cast<uint2*>(bdst + o) =
                    make_uint2(pkh(pv[p].x * w, pv[p].y * w), pkh(pv[p].z * w, pv[p].w * w));
            }
        }
        __syncthreads();
    }
}

extern "C" void kernel_launch(void* const* d_in, const int* in_sizes, int n_in,
                              void* d_out, int out_size) {
    const float* k   = (const float*)d_in[0];
    const float* src = (const float*)d_in[1];
    const float* dst = (const float*)d_in[2];
    float*       out = (float*)d_out;

    cudaFuncSetAttribute(mha_hmma2_kernel,
                         cudaFuncAttributeMaxDynamicSharedMemorySize, SMEM_TOTAL);
    (void)in_sizes; (void)n_in; (void)out_size;

    dim3 grid(LEN / 128, BHN);
    mha_hmma2_kernel<<<grid, 256, SMEM_TOTAL>>>(k, src, dst, out);
}